// round 3
// baseline (speedup 1.0000x reference)
#include <cuda_runtime.h>
#include <cuda_bf16.h>

// CubePad: x [6N, C, 256, 256] -> out [6N, C, 258, 258]
// Face order: 0 front, 1 right, 2 back, 3 left, 4 top, 5 down.
//
// One warp per output row (258 rows per face-channel). Middle rows (r=1..256)
// are fully vectorized: aligned LDG.128 of the input row, STG.128 of the whole
// output row including the left/right border values (row 16B-alignment
// alternates with row parity -> two store layouts). Rows 0 and 257 are the
// top/down plate gathers, handled scalar (tiny fraction of traffic).

#define Hh 256
#define Ww 256
#define Cc 64
#define HP 258
#define WP 258
#define FACE_IN  (Hh * Ww)
#define FACE_OUT (HP * WP)

__global__ __launch_bounds__(256) void cubepad_row(
    const float* __restrict__ in, float* __restrict__ out, int total_warps)
{
    int gw   = (blockIdx.x * blockDim.x + threadIdx.x) >> 5;
    int lane = threadIdx.x & 31;
    if (gw >= total_warps) return;

    int r   = gw % HP;          // output row 0..257
    int nfc = gw / HP;
    int c   = nfc % Cc;
    int nf  = nfc / Cc;
    int f   = nf % 6;
    int n   = nf / 6;

    const float* base  = in + ((size_t)(n * 6) * Cc + c) * FACE_IN;
    const float* front = base + (size_t)0 * Cc * FACE_IN;
    const float* right = base + (size_t)1 * Cc * FACE_IN;
    const float* back  = base + (size_t)2 * Cc * FACE_IN;
    const float* left  = base + (size_t)3 * Cc * FACE_IN;
    const float* top   = base + (size_t)4 * Cc * FACE_IN;
    const float* down  = base + (size_t)5 * Cc * FACE_IN;

    float* orow = out + (size_t)nfc * FACE_OUT + (size_t)r * WP;

    if (r >= 1 && r <= Hh) {
        // ---- middle row: vectorized copy + 2 border gathers ----
        int h = r - 1;
        const float* faces[6] = {front, right, back, left, top, down};
        const float* irow = faces[f] + (size_t)h * Ww;

        float4 v1 = reinterpret_cast<const float4*>(irow)[lane * 2];
        float4 v2 = reinterpret_cast<const float4*>(irow)[lane * 2 + 1];

        // border values (uniform across warp -> broadcast loads)
        float lval, rval;
        switch (f) {
            case 0: lval = left [h * Ww + (Ww - 1)]; rval = right[h * Ww];                 break;
            case 1: lval = front[h * Ww + (Ww - 1)]; rval = back [h * Ww];                 break;
            case 2: lval = right[h * Ww + (Ww - 1)]; rval = left [h * Ww];                 break;
            case 3: lval = back [h * Ww + (Ww - 1)]; rval = front[h * Ww];                 break;
            case 4: lval = left [h];                 rval = right[(Ww - 1 - h)];           break;
            default:lval = left [(Hh-1)*Ww + (Ww-1-h)]; rval = right[(Hh-1)*Ww + h];       break;
        }

        if ((r & 1) == 0) {
            // even row: orow is 16B aligned. Vectors cover cols 0..255,
            // leftover cols 256,257 via STG.64 (byte 1024, 16B aligned).
            float prev = __shfl_up_sync(0xffffffffu, v2.w, 1);   // in[8t-1]
            float4 o1 = make_float4(lane == 0 ? lval : prev, v1.x, v1.y, v1.z);
            float4 o2 = make_float4(v1.w, v2.x, v2.y, v2.z);
            reinterpret_cast<float4*>(orow)[lane * 2]     = o1;
            reinterpret_cast<float4*>(orow)[lane * 2 + 1] = o2;
            if (lane == 31)
                *reinterpret_cast<float2*>(orow + 256) = make_float2(v2.w, rval);
        } else {
            // odd row: orow+2 is 16B aligned. Vectors cover cols 2..257,
            // leftover cols 0,1 via STG.64 (8B aligned).
            float nxt = __shfl_down_sync(0xffffffffu, v1.x, 1);  // in[8t+8]
            float4 o1 = make_float4(v1.y, v1.z, v1.w, v2.x);
            float4 o2 = make_float4(v2.y, v2.z, v2.w, lane == 31 ? rval : nxt);
            reinterpret_cast<float4*>(orow + 2)[lane * 2]     = o1;
            reinterpret_cast<float4*>(orow + 2)[lane * 2 + 1] = o2;
            if (lane == 0)
                *reinterpret_cast<float2*>(orow) = make_float2(lval, v1.x);
        }
    } else {
        // ---- top (r==0) / bottom (r==257) plate rows: scalar gather ----
        bool is_top = (r == 0);
        for (int col = lane; col < WP; col += 32) {
            int w = col - 1;
            if (w < 0) w = 0;
            if (w > Ww - 1) w = Ww - 1;
            float val;
            if (is_top) {
                switch (f) {
                    case 0:  val = top[(Hh - 1) * Ww + w];             break;
                    case 1:  val = top[(Hh - 1 - w) * Ww + (Ww - 1)];  break;
                    case 2:  val = top[(Ww - 1 - w)];                  break;
                    case 3:  val = top[w * Ww];                        break;
                    case 4:  val = back[(Ww - 1 - w)];                 break;
                    default: val = front[(Hh - 1) * Ww + w];           break;
                }
            } else {
                switch (f) {
                    case 0:  val = down[w];                            break;
                    case 1:  val = down[w * Ww + (Ww - 1)];            break;
                    case 2:  val = down[(Hh - 1) * Ww + (Ww - 1 - w)]; break;
                    case 3:  val = down[(Hh - 1 - w) * Ww];            break;
                    case 4:  val = front[w];                           break;
                    default: val = back[(Hh - 1) * Ww + (Ww - 1 - w)]; break;
                }
            }
            orow[col] = val;
        }
    }
}

extern "C" void kernel_launch(void* const* d_in, const int* in_sizes, int n_in,
                              void* d_out, int out_size)
{
    const float* x = (const float*)d_in[0];
    float* out = (float*)d_out;

    int total_in = in_sizes[0];                 // 6N * C * H * W
    int nf = total_in / (Cc * Hh * Ww);         // 6N

    int total_warps = nf * Cc * HP;             // one warp per output row
    int blocks = (total_warps * 32 + 255) / 256;
    cubepad_row<<<blocks, 256>>>(x, out, total_warps);
}

// round 4
// speedup vs baseline: 1.2546x; 1.2546x over previous
#include <cuda_runtime.h>
#include <cuda_bf16.h>

// CubePad: x [6N, C, 256, 256] -> out [6N, C, 258, 258]
// Face order: 0 front, 1 right, 2 back, 3 left, 4 top, 5 down.
//
// One warp per 4 consecutive middle output rows of one face-channel (plus
// 2 extra warps per face-channel for the top/down plate rows). Middle rows
// are written entirely with 16B stores (row alignment alternates with row
// parity), border values fused into the same stores. All source pointers are
// resolved by switches into scalar (ptr, stride) pairs -- no indexed local
// arrays, no LDL.

#define Hh 256
#define Ww 256
#define Cc 64
#define HP 258
#define WP 258
#define FACE_IN  (Hh * Ww)
#define FACE_OUT (HP * WP)
#define GROUPS   66   // 64 groups of 4 middle rows + row0 + row257

__device__ __forceinline__ void store_even_row(
    float* orow, float4 v1, float4 v2, float lval, float rval, int lane)
{
    // even row: orow 16B aligned; vectors cover cols 0..255, STG.64 leftover
    float prev = __shfl_up_sync(0xffffffffu, v2.w, 1);
    float4 o1 = make_float4(lane == 0 ? lval : prev, v1.x, v1.y, v1.z);
    float4 o2 = make_float4(v1.w, v2.x, v2.y, v2.z);
    reinterpret_cast<float4*>(orow)[lane * 2]     = o1;
    reinterpret_cast<float4*>(orow)[lane * 2 + 1] = o2;
    if (lane == 31)
        *reinterpret_cast<float2*>(orow + 256) = make_float2(v2.w, rval);
}

__device__ __forceinline__ void store_odd_row(
    float* orow, float4 v1, float4 v2, float lval, float rval, int lane)
{
    // odd row: orow+2 16B aligned; vectors cover cols 2..257, STG.64 leftover
    float nxt = __shfl_down_sync(0xffffffffu, v1.x, 1);
    float4 o1 = make_float4(v1.y, v1.z, v1.w, v2.x);
    float4 o2 = make_float4(v2.y, v2.z, v2.w, lane == 31 ? rval : nxt);
    reinterpret_cast<float4*>(orow + 2)[lane * 2]     = o1;
    reinterpret_cast<float4*>(orow + 2)[lane * 2 + 1] = o2;
    if (lane == 0)
        *reinterpret_cast<float2*>(orow) = make_float2(lval, v1.x);
}

__global__ __launch_bounds__(256) void cubepad_v4(
    const float* __restrict__ in, float* __restrict__ out, int total_warps)
{
    int gw   = (blockIdx.x * blockDim.x + threadIdx.x) >> 5;
    int lane = threadIdx.x & 31;
    if (gw >= total_warps) return;

    int g   = gw % GROUPS;
    int nfc = gw / GROUPS;
    int c   = nfc % Cc;
    int nf  = nfc / Cc;
    int f   = nf % 6;
    int n   = nf / 6;

    const float* base  = in + ((size_t)(n * 6) * Cc + c) * FACE_IN;
    const float* front = base + (size_t)0 * Cc * FACE_IN;
    const float* right = base + (size_t)1 * Cc * FACE_IN;
    const float* back  = base + (size_t)2 * Cc * FACE_IN;
    const float* left  = base + (size_t)3 * Cc * FACE_IN;
    const float* top   = base + (size_t)4 * Cc * FACE_IN;
    const float* down  = base + (size_t)5 * Cc * FACE_IN;

    float* oface = out + (size_t)nfc * FACE_OUT;

    if (g < 64) {
        // ---- 4 middle rows: r = 4g+1 .. 4g+4 (h = 4g .. 4g+3) ----
        const float* self = base + (size_t)f * Cc * FACE_IN;

        // border source: val(h) = ptr[h * str]
        const float* lptr; int lstr;
        const float* rptr; int rstr;
        switch (f) {
            case 0: lptr = left  + (Ww-1); lstr = Ww; rptr = right; rstr = Ww; break;
            case 1: lptr = front + (Ww-1); lstr = Ww; rptr = back;  rstr = Ww; break;
            case 2: lptr = right + (Ww-1); lstr = Ww; rptr = left;  rstr = Ww; break;
            case 3: lptr = back  + (Ww-1); lstr = Ww; rptr = front; rstr = Ww; break;
            case 4: lptr = left;           lstr = 1;
                    rptr = right + (Ww-1); rstr = -1; break;
            default:lptr = left + (Hh-1)*Ww + (Ww-1); lstr = -1;
                    rptr = right + (Hh-1)*Ww;         rstr = 1;  break;
        }

        int h0 = g * 4;
        #pragma unroll
        for (int i = 0; i < 2; i++) {
            int ho = h0 + 2 * i;          // odd output row r = ho+1
            int he = ho + 1;              // even output row r = he+1

            const float4* ivo = reinterpret_cast<const float4*>(self + (size_t)ho * Ww);
            const float4* ive = reinterpret_cast<const float4*>(self + (size_t)he * Ww);
            float4 a1 = ivo[lane * 2];
            float4 a2 = ivo[lane * 2 + 1];
            float4 b1 = ive[lane * 2];
            float4 b2 = ive[lane * 2 + 1];
            float la = lptr[ho * lstr], ra = rptr[ho * rstr];
            float lb = lptr[he * lstr], rb = rptr[he * rstr];

            store_odd_row (oface + (size_t)(ho + 1) * WP, a1, a2, la, ra, lane);
            store_even_row(oface + (size_t)(he + 1) * WP, b1, b2, lb, rb, lane);
        }
    } else {
        // ---- top (g==64 -> r=0) / bottom (g==65 -> r=257) plate rows ----
        bool is_top = (g == 64);
        float* orow = oface + (is_top ? 0 : (size_t)(HP - 1) * WP);
        for (int col = lane; col < WP; col += 32) {
            int w = col - 1;
            if (w < 0) w = 0;
            if (w > Ww - 1) w = Ww - 1;
            float val;
            if (is_top) {
                switch (f) {
                    case 0:  val = top[(Hh - 1) * Ww + w];             break;
                    case 1:  val = top[(Hh - 1 - w) * Ww + (Ww - 1)];  break;
                    case 2:  val = top[(Ww - 1 - w)];                  break;
                    case 3:  val = top[w * Ww];                        break;
                    case 4:  val = back[(Ww - 1 - w)];                 break;
                    default: val = front[(Hh - 1) * Ww + w];           break;
                }
            } else {
                switch (f) {
                    case 0:  val = down[w];                            break;
                    case 1:  val = down[w * Ww + (Ww - 1)];            break;
                    case 2:  val = down[(Hh - 1) * Ww + (Ww - 1 - w)]; break;
                    case 3:  val = down[(Hh - 1 - w) * Ww];            break;
                    case 4:  val = front[w];                           break;
                    default: val = back[(Hh - 1) * Ww + (Ww - 1 - w)]; break;
                }
            }
            orow[col] = val;
        }
    }
}

extern "C" void kernel_launch(void* const* d_in, const int* in_sizes, int n_in,
                              void* d_out, int out_size)
{
    const float* x = (const float*)d_in[0];
    float* out = (float*)d_out;

    int total_in = in_sizes[0];                 // 6N * C * H * W
    int nf = total_in / (Cc * Hh * Ww);         // 6N

    int total_warps = nf * Cc * GROUPS;
    int blocks = (total_warps * 32 + 255) / 256;
    cubepad_v4<<<blocks, 256>>>(x, out, total_warps);
}

// round 5
// speedup vs baseline: 1.3224x; 1.0540x over previous
#include <cuda_runtime.h>
#include <cuda_bf16.h>

// CubePad: x [6N, C, 256, 256] -> out [6N, C, 258, 258]
// Face order: 0 front, 1 right, 2 back, 3 left, 4 top, 5 down.
//
// One warp per PAIR of middle output rows (odd r then even r), full-row
// STG.128 stores with parity-dependent layout, border values fused into the
// row stores. All 4 row loads batched before any store (MLP). Low register
// footprint (32-bit offsets, single base pointer) for high occupancy.

#define Hh 256
#define Ww 256
#define Cc 64
#define HP 258
#define WP 258
#define FACE_IN  (Hh * Ww)
#define FACE_OUT (HP * WP)
#define CF       (Cc * FACE_IN)   // face stride in floats
#define GROUPS   130              // 128 row-pairs + top plate + down plate

__device__ __forceinline__ void store_even_row(
    float* orow, float4 v1, float4 v2, float lval, float rval, int lane)
{
    // even r: orow 16B aligned; vectors cover cols 0..255, STG.64 leftover
    float prev = __shfl_up_sync(0xffffffffu, v2.w, 1);
    float4 o1 = make_float4(lane == 0 ? lval : prev, v1.x, v1.y, v1.z);
    float4 o2 = make_float4(v1.w, v2.x, v2.y, v2.z);
    reinterpret_cast<float4*>(orow)[lane * 2]     = o1;
    reinterpret_cast<float4*>(orow)[lane * 2 + 1] = o2;
    if (lane == 31)
        *reinterpret_cast<float2*>(orow + 256) = make_float2(v2.w, rval);
}

__device__ __forceinline__ void store_odd_row(
    float* orow, float4 v1, float4 v2, float lval, float rval, int lane)
{
    // odd r: orow+2 16B aligned; vectors cover cols 2..257, STG.64 leftover
    float nxt = __shfl_down_sync(0xffffffffu, v1.x, 1);
    float4 o1 = make_float4(v1.y, v1.z, v1.w, v2.x);
    float4 o2 = make_float4(v2.y, v2.z, v2.w, lane == 31 ? rval : nxt);
    reinterpret_cast<float4*>(orow + 2)[lane * 2]     = o1;
    reinterpret_cast<float4*>(orow + 2)[lane * 2 + 1] = o2;
    if (lane == 0)
        *reinterpret_cast<float2*>(orow) = make_float2(lval, v1.x);
}

__global__ void __launch_bounds__(256, 6) cubepad_v5(
    const float* __restrict__ in, float* __restrict__ out, int total_warps)
{
    int gw   = (blockIdx.x * blockDim.x + threadIdx.x) >> 5;
    int lane = threadIdx.x & 31;
    if (gw >= total_warps) return;

    int g   = gw % GROUPS;
    int nfc = gw / GROUPS;
    int c   = nfc % Cc;
    int nf  = nfc / Cc;
    int f   = nf % 6;
    int n   = nf / 6;

    const float* base = in + (n * 6 * Cc + c) * FACE_IN;  // face 0 of this cube/channel
    float* oface = out + nfc * FACE_OUT;

    if (g < 128) {
        // ---- row pair: h = 2g (odd output row), 2g+1 (even output row) ----
        int ho = g * 2;
        int he = ho + 1;
        const float* self = base + f * CF + ho * Ww;

        // batch all 4 vector loads (independent -> MLP 4)
        float4 a1 = reinterpret_cast<const float4*>(self)[lane * 2];
        float4 a2 = reinterpret_cast<const float4*>(self)[lane * 2 + 1];
        float4 b1 = reinterpret_cast<const float4*>(self + Ww)[lane * 2];
        float4 b2 = reinterpret_cast<const float4*>(self + Ww)[lane * 2 + 1];

        // border values (uniform across warp)
        float la, ra, lb, rb;
        switch (f) {
            case 0: la = base[3*CF + ho*Ww + (Ww-1)]; lb = base[3*CF + he*Ww + (Ww-1)];
                    ra = base[1*CF + ho*Ww];          rb = base[1*CF + he*Ww];          break;
            case 1: la = base[0*CF + ho*Ww + (Ww-1)]; lb = base[0*CF + he*Ww + (Ww-1)];
                    ra = base[2*CF + ho*Ww];          rb = base[2*CF + he*Ww];          break;
            case 2: la = base[1*CF + ho*Ww + (Ww-1)]; lb = base[1*CF + he*Ww + (Ww-1)];
                    ra = base[3*CF + ho*Ww];          rb = base[3*CF + he*Ww];          break;
            case 3: la = base[2*CF + ho*Ww + (Ww-1)]; lb = base[2*CF + he*Ww + (Ww-1)];
                    ra = base[0*CF + ho*Ww];          rb = base[0*CF + he*Ww];          break;
            case 4: la = base[3*CF + ho];             lb = base[3*CF + he];
                    ra = base[1*CF + (Ww-1-ho)];      rb = base[1*CF + (Ww-1-he)];      break;
            default:la = base[3*CF + (Hh-1)*Ww + (Ww-1-ho)];
                    lb = base[3*CF + (Hh-1)*Ww + (Ww-1-he)];
                    ra = base[1*CF + (Hh-1)*Ww + ho];
                    rb = base[1*CF + (Hh-1)*Ww + he];                                   break;
        }

        store_odd_row (oface + (ho + 1) * WP, a1, a2, la, ra, lane);
        store_even_row(oface + (he + 1) * WP, b1, b2, lb, rb, lane);
    } else {
        // ---- top (g==128 -> r=0) / bottom (g==129 -> r=257) plate rows ----
        bool is_top = (g == 128);
        const float* front = base;
        const float* right = base + 1 * CF;
        const float* back  = base + 2 * CF;
        const float* down  = base + 5 * CF;
        const float* top   = base + 4 * CF;
        float* orow = oface + (is_top ? 0 : (HP - 1) * WP);
        for (int col = lane; col < WP; col += 32) {
            int w = col - 1;
            if (w < 0) w = 0;
            if (w > Ww - 1) w = Ww - 1;
            float val;
            if (is_top) {
                switch (f) {
                    case 0:  val = top[(Hh - 1) * Ww + w];             break;
                    case 1:  val = top[(Hh - 1 - w) * Ww + (Ww - 1)];  break;
                    case 2:  val = top[(Ww - 1 - w)];                  break;
                    case 3:  val = top[w * Ww];                        break;
                    case 4:  val = back[(Ww - 1 - w)];                 break;
                    default: val = front[(Hh - 1) * Ww + w];           break;
                }
            } else {
                switch (f) {
                    case 0:  val = down[w];                            break;
                    case 1:  val = down[w * Ww + (Ww - 1)];            break;
                    case 2:  val = down[(Hh - 1) * Ww + (Ww - 1 - w)]; break;
                    case 3:  val = down[(Hh - 1 - w) * Ww];            break;
                    case 4:  val = front[w];                           break;
                    default: val = back[(Hh - 1) * Ww + (Ww - 1 - w)]; break;
                }
            }
            orow[col] = val;
        }
    }
}

extern "C" void kernel_launch(void* const* d_in, const int* in_sizes, int n_in,
                              void* d_out, int out_size)
{
    const float* x = (const float*)d_in[0];
    float* out = (float*)d_out;

    int total_in = in_sizes[0];                 // 6N * C * H * W
    int nf = total_in / (Cc * Hh * Ww);         // 6N

    int total_warps = nf * Cc * GROUPS;
    int blocks = (total_warps * 32 + 255) / 256;
    cubepad_v5<<<blocks, 256>>>(x, out, total_warps);
}